// round 3
// baseline (speedup 1.0000x reference)
#include <cuda_runtime.h>

#define BB 4
#define NN 4096
#define DD 16
#define CC 128
#define LOG2E 1.4426950408889634f
#define NT3 64   /* pass3 row tiles: 4096/64 */

typedef unsigned long long ull;

__device__ __align__(16) float g_Q[BB * NN * DD];
__device__ __align__(16) float g_K[BB * NN * DD];   // pre-scaled by log2(e)
__device__ __align__(16) float g_V[BB * NN * DD];
__device__ float g_rowinv[BB * NN];
__device__ float g_colinv[BB * NN];
__device__ float g_T[BB * DD * NN];
__device__ float g_part[BB * NT3 * 8];

__device__ __forceinline__ ull pack2(float lo, float hi) {
    ull r; asm("mov.b64 %0, {%1, %2};" : "=l"(r) : "f"(lo), "f"(hi)); return r;
}
__device__ __forceinline__ void unpack2(ull v, float& lo, float& hi) {
    asm("mov.b64 {%0, %1}, %2;" : "=f"(lo), "=f"(hi) : "l"(v));
}
__device__ __forceinline__ ull fma2(ull a, ull b, ull c) {
    ull d; asm("fma.rn.f32x2 %0, %1, %2, %3;" : "=l"(d) : "l"(a), "l"(b), "l"(c)); return d;
}
__device__ __forceinline__ ull add2(ull a, ull b) {
    ull d; asm("add.rn.f32x2 %0, %1, %2;" : "=l"(d) : "l"(a), "l"(b)); return d;
}
__device__ __forceinline__ float ex2(float x) {
    float y; asm("ex2.approx.ftz.f32 %0, %1;" : "=f"(y) : "f"(x)); return y;
}

__device__ __forceinline__ float dotrr(const ull* q, const ull* kk) {
    ull a0 = fma2(q[0], kk[0], 0ULL);
    ull a1 = fma2(q[1], kk[1], 0ULL);
#pragma unroll
    for (int i = 1; i < 4; i++) {
        a0 = fma2(q[2 * i], kk[2 * i], a0);
        a1 = fma2(q[2 * i + 1], kk[2 * i + 1], a1);
    }
    ull s = add2(a0, a1);
    float x, y; unpack2(s, x, y);
    return x + y;
}

__device__ __forceinline__ void load_rowpack(ull* dst, const float* base, int nrows) {
    const ulonglong2* p = (const ulonglong2*)base;
    for (int r = 0; r < nrows; r++)
#pragma unroll
        for (int i = 0; i < 4; i++) {
            ulonglong2 t = p[r * 4 + i];
            dst[r * 8 + 2 * i] = t.x; dst[r * 8 + 2 * i + 1] = t.y;
        }
}

// ---------------------------------------------------------------------------
// Kernel 1: projections. Q raw; K scaled by log2(e); V = wv@x + b_v + pos.
// ---------------------------------------------------------------------------
__global__ void proj_kernel(const float* __restrict__ x_q, const float* __restrict__ x_kv,
                            const float* __restrict__ xyz_q, const float* __restrict__ xyz_kv,
                            const float* __restrict__ w_qk, const float* __restrict__ w_v,
                            const float* __restrict__ b_v,
                            const float* __restrict__ w_pos_q, const float* __restrict__ w_pos_kv) {
    __shared__ __align__(16) float s_wqk[CC][DD];
    __shared__ __align__(16) float s_wv[CC][DD];
    const int b = blockIdx.z;
    const int isKV = blockIdx.y;
    const int n = blockIdx.x * 128 + threadIdx.x;
    for (int i = threadIdx.x; i < CC * DD; i += 128) {
        int d = i / CC, c = i % CC;
        s_wqk[c][d] = w_qk[i];
        s_wv[c][d] = w_v[i];
    }
    __syncthreads();
    if (isKV == 0) {
        float p0 = xyz_q[(b * 3 + 0) * NN + n];
        float p1 = xyz_q[(b * 3 + 1) * NN + n];
        float p2 = xyz_q[(b * 3 + 2) * NN + n];
        float acc[DD];
#pragma unroll
        for (int d = 0; d < DD; d++)
            acc[d] = w_pos_q[d * 3] * p0 + w_pos_q[d * 3 + 1] * p1 + w_pos_q[d * 3 + 2] * p2;
        const float* xp = x_q + (size_t)b * CC * NN + n;
#pragma unroll 4
        for (int c = 0; c < CC; c++) {
            float xv = xp[(size_t)c * NN];
            const float4* w4 = (const float4*)s_wqk[c];
#pragma unroll
            for (int i = 0; i < 4; i++) {
                float4 w = w4[i];
                acc[4 * i + 0] += w.x * xv; acc[4 * i + 1] += w.y * xv;
                acc[4 * i + 2] += w.z * xv; acc[4 * i + 3] += w.w * xv;
            }
        }
        float4* qp = (float4*)(g_Q + ((size_t)(b * NN + n)) * DD);
#pragma unroll
        for (int i = 0; i < 4; i++)
            qp[i] = make_float4(acc[4 * i], acc[4 * i + 1], acc[4 * i + 2], acc[4 * i + 3]);
    } else {
        float p0 = xyz_kv[(b * 3 + 0) * NN + n];
        float p1 = xyz_kv[(b * 3 + 1) * NN + n];
        float p2 = xyz_kv[(b * 3 + 2) * NN + n];
        float ak[DD], av[DD];
#pragma unroll
        for (int d = 0; d < DD; d++) {
            float pos = w_pos_kv[d * 3] * p0 + w_pos_kv[d * 3 + 1] * p1 + w_pos_kv[d * 3 + 2] * p2;
            ak[d] = pos;
            av[d] = pos + b_v[d];
        }
        const float* xp = x_kv + (size_t)b * CC * NN + n;
#pragma unroll 2
        for (int c = 0; c < CC; c++) {
            float xv = xp[(size_t)c * NN];
            const float4* wq4 = (const float4*)s_wqk[c];
            const float4* wv4 = (const float4*)s_wv[c];
#pragma unroll
            for (int i = 0; i < 4; i++) {
                float4 wq = wq4[i], wv = wv4[i];
                ak[4 * i + 0] += wq.x * xv; ak[4 * i + 1] += wq.y * xv;
                ak[4 * i + 2] += wq.z * xv; ak[4 * i + 3] += wq.w * xv;
                av[4 * i + 0] += wv.x * xv; av[4 * i + 1] += wv.y * xv;
                av[4 * i + 2] += wv.z * xv; av[4 * i + 3] += wv.w * xv;
            }
        }
        float4* kp = (float4*)(g_K + ((size_t)(b * NN + n)) * DD);
        float4* vp = (float4*)(g_V + ((size_t)(b * NN + n)) * DD);
#pragma unroll
        for (int i = 0; i < 4; i++) {
            kp[i] = make_float4(ak[4 * i] * LOG2E, ak[4 * i + 1] * LOG2E,
                                ak[4 * i + 2] * LOG2E, ak[4 * i + 3] * LOG2E);
            vp[i] = make_float4(av[4 * i], av[4 * i + 1], av[4 * i + 2], av[4 * i + 3]);
        }
    }
}

// ---------------------------------------------------------------------------
// Kernel 2: rowsum. 512 thr / 16 warps. Lane = 4 rows; warp = 256-wide m-range.
// ---------------------------------------------------------------------------
__global__ __launch_bounds__(512, 1) void rowsum_kernel() {
    __shared__ __align__(16) float sk[16][32 * DD];
    __shared__ float sred[16][128];
    const int tid = threadIdx.x, lane = tid & 31, w = tid >> 5;
    const int b = blockIdx.y;
    const int row0 = blockIdx.x * 128 + lane * 4;

    ull qr[32];
    load_rowpack(qr, g_Q + ((size_t)(b * NN + row0)) * DD, 4);

    const float* kbase = g_K + ((size_t)b * NN + (size_t)w * 256) * DD;
    float sum[4] = {0.f, 0.f, 0.f, 0.f};
    for (int it = 0; it < 8; ++it) {
        __syncwarp();
        {
            float4* dst = (float4*)sk[w];
            const float4* src = (const float4*)(kbase + it * 32 * DD);
#pragma unroll
            for (int j = 0; j < 4; j++) dst[lane + j * 32] = src[lane + j * 32];
        }
        __syncwarp();
#pragma unroll 4
        for (int mm = 0; mm < 32; ++mm) {
            ull kk[8];
            const ulonglong2* k2 = (const ulonglong2*)(sk[w] + mm * DD);
#pragma unroll
            for (int i = 0; i < 4; i++) { ulonglong2 t = k2[i]; kk[2 * i] = t.x; kk[2 * i + 1] = t.y; }
#pragma unroll
            for (int r = 0; r < 4; r++) sum[r] += ex2(dotrr(qr + r * 8, kk));
        }
    }
#pragma unroll
    for (int r = 0; r < 4; r++) sred[w][lane * 4 + r] = sum[r];
    __syncthreads();
    if (tid < 128) {
        float tot = 0.f;
#pragma unroll
        for (int j = 0; j < 16; j++) tot += sred[j][tid];
        g_rowinv[b * NN + blockIdx.x * 128 + tid] = 1.0f / tot;
    }
}

// ---------------------------------------------------------------------------
// Kernel 3: colsum. 512 thr / 16 warps. Lane = 4 cols; warp = 256-wide n-range.
// ---------------------------------------------------------------------------
__global__ __launch_bounds__(512, 1) void colsum_kernel() {
    __shared__ __align__(16) float sq[16][32 * DD];
    __shared__ float sri[16][32];
    __shared__ float sred[16][128];
    const int tid = threadIdx.x, lane = tid & 31, w = tid >> 5;
    const int b = blockIdx.y;
    const int col0 = blockIdx.x * 128 + lane * 4;

    ull kr[32];
    load_rowpack(kr, g_K + ((size_t)(b * NN + col0)) * DD, 4);

    const float* qbase = g_Q + ((size_t)b * NN + (size_t)w * 256) * DD;
    const float* ribase = g_rowinv + b * NN + w * 256;
    float sum[4] = {0.f, 0.f, 0.f, 0.f};
    for (int it = 0; it < 8; ++it) {
        __syncwarp();
        {
            float4* dst = (float4*)sq[w];
            const float4* src = (const float4*)(qbase + it * 32 * DD);
#pragma unroll
            for (int j = 0; j < 4; j++) dst[lane + j * 32] = src[lane + j * 32];
            sri[w][lane] = ribase[it * 32 + lane];
        }
        __syncwarp();
#pragma unroll 4
        for (int nn2 = 0; nn2 < 32; ++nn2) {
            ull kk[8];
            const ulonglong2* q2 = (const ulonglong2*)(sq[w] + nn2 * DD);
#pragma unroll
            for (int i = 0; i < 4; i++) { ulonglong2 t = q2[i]; kk[2 * i] = t.x; kk[2 * i + 1] = t.y; }
            float ri = sri[w][nn2];
#pragma unroll
            for (int r = 0; r < 4; r++) sum[r] += ex2(dotrr(kr + r * 8, kk)) * ri;
        }
    }
#pragma unroll
    for (int r = 0; r < 4; r++) sred[w][lane * 4 + r] = sum[r];
    __syncthreads();
    if (tid < 128) {
        float tot = 0.f;
#pragma unroll
        for (int j = 0; j < 16; j++) tot += sred[j][tid];
        g_colinv[b * NN + blockIdx.x * 128 + tid] = 1.0f / (1e-9f + tot);
    }
}

// ---------------------------------------------------------------------------
// Kernel 4: AV sweep + w_t transform + GN partial stats.
// 64 rows/block (2 rows/lane), 8 warps, 2 CTAs/SM.
// ---------------------------------------------------------------------------
__global__ __launch_bounds__(256, 2) void pass3_kernel(const float* __restrict__ w_t,
                                                       const float* __restrict__ b_t) {
    __shared__ __align__(16) float sbig[8192];   // 32KB: per-warp k/v tiles, then xr slots
    __shared__ float sci[8][32];
    __shared__ float swt[256];
    __shared__ float sred[512];
    const int tid = threadIdx.x, lane = tid & 31, w = tid >> 5;
    const int b = blockIdx.y;
    const int row0 = blockIdx.x * 64 + lane * 2;

    swt[tid] = w_t[tid];

    ull qr[16];
    load_rowpack(qr, g_Q + ((size_t)(b * NN + row0)) * DD, 2);

    const float* kbase = g_K + ((size_t)b * NN + (size_t)w * 512) * DD;
    const float* vbase = g_V + ((size_t)b * NN + (size_t)w * 512) * DD;
    const float* cibase = g_colinv + b * NN + w * 512;
    float* skw = sbig + w * 1024;        // 32 m x 16
    float* svw = skw + 512;

    ull xr[16];
#pragma unroll
    for (int i = 0; i < 16; i++) xr[i] = 0ULL;

    for (int it = 0; it < 16; ++it) {
        __syncwarp();
        {
            float4* dk = (float4*)skw;
            float4* dv = (float4*)svw;
            const float4* srck = (const float4*)(kbase + it * 32 * DD);
            const float4* srcv = (const float4*)(vbase + it * 32 * DD);
#pragma unroll
            for (int j = 0; j < 4; j++) {
                dk[lane + j * 32] = srck[lane + j * 32];
                dv[lane + j * 32] = srcv[lane + j * 32];
            }
            sci[w][lane] = cibase[it * 32 + lane];
        }
        __syncwarp();
#pragma unroll 2
        for (int mm = 0; mm < 32; ++mm) {
            ull kk[8];
            const ulonglong2* k2 = (const ulonglong2*)(skw + mm * DD);
#pragma unroll
            for (int i = 0; i < 4; i++) { ulonglong2 t = k2[i]; kk[2 * i] = t.x; kk[2 * i + 1] = t.y; }
            float ci = sci[w][mm];
            float w0 = ex2(dotrr(qr, kk)) * ci;
            float w1 = ex2(dotrr(qr + 8, kk)) * ci;
            ull vv[8];
            const ulonglong2* v2 = (const ulonglong2*)(svw + mm * DD);
#pragma unroll
            for (int i = 0; i < 4; i++) { ulonglong2 t = v2[i]; vv[2 * i] = t.x; vv[2 * i + 1] = t.y; }
            ull w20 = pack2(w0, w0);
            ull w21 = pack2(w1, w1);
#pragma unroll
            for (int i = 0; i < 8; i++) {
                xr[i] = fma2(w20, vv[i], xr[i]);
                xr[8 + i] = fma2(w21, vv[i], xr[8 + i]);
            }
        }
    }

    // reduce xr across 8 warps: 4 slots x 64 rows x 16 floats in sbig
    __syncthreads();
    if (w >= 4) {
        ull* d = (ull*)(sbig + ((size_t)(w - 4) * 64 + lane * 2) * DD);
#pragma unroll
        for (int i = 0; i < 16; i++) d[i] = xr[i];
    }
    __syncthreads();
    if (w < 4) {
        ull* d = (ull*)(sbig + ((size_t)w * 64 + lane * 2) * DD);
#pragma unroll
        for (int i = 0; i < 16; i++) d[i] = add2(d[i], xr[i]);
    }
    __syncthreads();

    if (tid < 64) {
        const int row = blockIdx.x * 64 + tid;
        float rinv = g_rowinv[b * NN + row];
        float xrf[DD];
        const float* s0 = sbig + tid * DD;
#pragma unroll
        for (int d = 0; d < DD; d++)
            xrf[d] = (s0[d] + s0[1024 + d] + s0[2048 + d] + s0[3072 + d]) * rinv;
        const float* qg = g_Q + ((size_t)(b * NN + row)) * DD;
        float diff[DD];
#pragma unroll
        for (int d = 0; d < DD; d++) diff[d] = qg[d] - xrf[d];
        float gs[4] = {0.f, 0.f, 0.f, 0.f}, gs2[4] = {0.f, 0.f, 0.f, 0.f};
#pragma unroll
        for (int o = 0; o < DD; o++) {
            float s = b_t[o];
#pragma unroll
            for (int d = 0; d < DD; d++) s += swt[o * DD + d] * diff[d];
            g_T[((size_t)(b * DD + o)) * NN + row] = s;
            gs[o >> 2] += s;
            gs2[o >> 2] += s * s;
        }
#pragma unroll
        for (int g = 0; g < 4; g++) {
            sred[tid * 8 + g] = gs[g];
            sred[tid * 8 + 4 + g] = gs2[g];
        }
    }
    __syncthreads();
    for (int s = 32; s > 0; s >>= 1) {
        if (tid < s) {
#pragma unroll
            for (int j = 0; j < 8; j++) sred[tid * 8 + j] += sred[(tid + s) * 8 + j];
        }
        __syncthreads();
    }
    if (tid < 8) g_part[((size_t)(b * NT3 + blockIdx.x)) * 8 + tid] = sred[tid];
}

// ---------------------------------------------------------------------------
// Kernel 5: finalize GN stats, relu, + q^T.
// ---------------------------------------------------------------------------
__global__ void final_kernel(const float* __restrict__ gamma, const float* __restrict__ beta,
                             float* __restrict__ out) {
    __shared__ float sq[128 * 17];
    __shared__ float ssc[DD], ssh[DD];
    const int b = blockIdx.y;
    const int tid = threadIdx.x;
    const int n0 = blockIdx.x * 128;
    if (tid < DD) {
        int g = tid >> 2;
        float s = 0.f, s2 = 0.f;
        for (int t = 0; t < NT3; t++) {
            s += g_part[(b * NT3 + t) * 8 + g];
            s2 += g_part[(b * NT3 + t) * 8 + 4 + g];
        }
        float cnt = (float)(4 * NN);
        float mean = s / cnt;
        float var = s2 / cnt - mean * mean;
        float inv = rsqrtf(var + 1e-5f);
        float sc = gamma[tid] * inv;
        ssc[tid] = sc;
        ssh[tid] = beta[tid] - mean * sc;
    }
    const float* qsrc = g_Q + ((size_t)(b * NN + n0)) * DD;
    for (int i = tid; i < 128 * DD; i += 256) sq[(i >> 4) * 17 + (i & 15)] = qsrc[i];
    __syncthreads();
    for (int i = tid; i < 128 * DD; i += 256) {
        int c = i >> 7, j = i & 127;
        size_t idx = ((size_t)(b * DD + c)) * NN + n0 + j;
        float tv = g_T[idx];
        float r = fmaxf(tv * ssc[c] + ssh[c], 0.f);
        out[idx] = r + sq[j * 17 + c];
    }
}

extern "C" void kernel_launch(void* const* d_in, const int* in_sizes, int n_in,
                              void* d_out, int out_size) {
    const float* x_q      = (const float*)d_in[0];
    const float* x_kv     = (const float*)d_in[1];
    const float* xyz_q    = (const float*)d_in[2];
    const float* xyz_kv   = (const float*)d_in[3];
    const float* w_qk     = (const float*)d_in[4];
    const float* w_v      = (const float*)d_in[5];
    const float* b_v      = (const float*)d_in[6];
    const float* w_t      = (const float*)d_in[7];
    const float* b_t      = (const float*)d_in[8];
    const float* gamma    = (const float*)d_in[9];
    const float* beta     = (const float*)d_in[10];
    const float* w_pos_q  = (const float*)d_in[11];
    const float* w_pos_kv = (const float*)d_in[12];
    float* out = (float*)d_out;

    proj_kernel<<<dim3(32, 2, BB), 128>>>(x_q, x_kv, xyz_q, xyz_kv, w_qk, w_v, b_v,
                                          w_pos_q, w_pos_kv);
    rowsum_kernel<<<dim3(32, BB), 512>>>();
    colsum_kernel<<<dim3(32, BB), 512>>>();
    pass3_kernel<<<dim3(NT3, BB), 256>>>(w_t, b_t);
    final_kernel<<<dim3(32, BB), 256>>>(gamma, beta, out);
}

// round 4
// speedup vs baseline: 1.0081x; 1.0081x over previous
#include <cuda_runtime.h>

#define BB 4
#define NN 4096
#define DD 16
#define CC 128
#define LOG2E 1.4426950408889634f
#define NT 32

typedef unsigned long long ull;

__device__ __align__(16) float g_Q[BB * NN * DD];
__device__ __align__(16) float g_K[BB * NN * DD];   // pre-scaled by log2(e)
__device__ __align__(16) float g_V[BB * NN * DD];
__device__ float g_rowinv[BB * NN];
__device__ float g_colinv[BB * NN];
__device__ float g_T[BB * DD * NN];
__device__ float g_part[BB * NT * 8];

__device__ __forceinline__ ull pack2(float lo, float hi) {
    ull r; asm("mov.b64 %0, {%1, %2};" : "=l"(r) : "f"(lo), "f"(hi)); return r;
}
__device__ __forceinline__ void unpack2(ull v, float& lo, float& hi) {
    asm("mov.b64 {%0, %1}, %2;" : "=f"(lo), "=f"(hi) : "l"(v));
}
__device__ __forceinline__ ull fma2(ull a, ull b, ull c) {
    ull d; asm("fma.rn.f32x2 %0, %1, %2, %3;" : "=l"(d) : "l"(a), "l"(b), "l"(c)); return d;
}
__device__ __forceinline__ ull add2(ull a, ull b) {
    ull d; asm("add.rn.f32x2 %0, %1, %2;" : "=l"(d) : "l"(a), "l"(b)); return d;
}
__device__ __forceinline__ float ex2(float x) {
    float y; asm("ex2.approx.ftz.f32 %0, %1;" : "=f"(y) : "f"(x)); return y;
}
__device__ __forceinline__ void cpa16(unsigned dst, const void* src) {
    asm volatile("cp.async.ca.shared.global [%0], [%1], 16;" :: "r"(dst), "l"(src));
}
__device__ __forceinline__ void cpa4(unsigned dst, const void* src) {
    asm volatile("cp.async.ca.shared.global [%0], [%1], 4;" :: "r"(dst), "l"(src));
}
__device__ __forceinline__ void cp_commit() { asm volatile("cp.async.commit_group;"); }
template <int N> __device__ __forceinline__ void cp_wait() {
    asm volatile("cp.async.wait_group %0;" :: "n"(N));
}

// 4-chain dot: depth-2 FMA chains + add2 tree.
__device__ __forceinline__ float dotrr(const ull* q, const ull* kk) {
    ull a0 = fma2(q[0], kk[0], 0ULL);
    ull a1 = fma2(q[1], kk[1], 0ULL);
    ull a2 = fma2(q[2], kk[2], 0ULL);
    ull a3 = fma2(q[3], kk[3], 0ULL);
    a0 = fma2(q[4], kk[4], a0);
    a1 = fma2(q[5], kk[5], a1);
    a2 = fma2(q[6], kk[6], a2);
    a3 = fma2(q[7], kk[7], a3);
    ull s = add2(add2(a0, a1), add2(a2, a3));
    float x, y; unpack2(s, x, y);
    return x + y;
}

__device__ __forceinline__ void load_rows4(ull* dst, const float* base) {
    const ulonglong2* p = (const ulonglong2*)base;
#pragma unroll
    for (int r = 0; r < 4; r++)
#pragma unroll
        for (int i = 0; i < 4; i++) {
            ulonglong2 t = p[r * 4 + i];
            dst[r * 8 + 2 * i] = t.x; dst[r * 8 + 2 * i + 1] = t.y;
        }
}
__device__ __forceinline__ void ldk(ull* kk, const float* p) {
    const ulonglong2* k2 = (const ulonglong2*)p;
#pragma unroll
    for (int i = 0; i < 4; i++) { ulonglong2 t = k2[i]; kk[2 * i] = t.x; kk[2 * i + 1] = t.y; }
}

// ---------------------------------------------------------------------------
// Kernel 1: projections. Q raw; K scaled by log2(e); V = wv@x + b_v + pos.
// ---------------------------------------------------------------------------
__global__ void proj_kernel(const float* __restrict__ x_q, const float* __restrict__ x_kv,
                            const float* __restrict__ xyz_q, const float* __restrict__ xyz_kv,
                            const float* __restrict__ w_qk, const float* __restrict__ w_v,
                            const float* __restrict__ b_v,
                            const float* __restrict__ w_pos_q, const float* __restrict__ w_pos_kv) {
    __shared__ __align__(16) float s_wqk[CC][DD];
    __shared__ __align__(16) float s_wv[CC][DD];
    const int b = blockIdx.z;
    const int isKV = blockIdx.y;
    const int n = blockIdx.x * 128 + threadIdx.x;
    for (int i = threadIdx.x; i < CC * DD; i += 128) {
        int d = i / CC, c = i % CC;
        s_wqk[c][d] = w_qk[i];
        s_wv[c][d] = w_v[i];
    }
    __syncthreads();
    if (isKV == 0) {
        float p0 = xyz_q[(b * 3 + 0) * NN + n];
        float p1 = xyz_q[(b * 3 + 1) * NN + n];
        float p2 = xyz_q[(b * 3 + 2) * NN + n];
        float acc[DD];
#pragma unroll
        for (int d = 0; d < DD; d++)
            acc[d] = w_pos_q[d * 3] * p0 + w_pos_q[d * 3 + 1] * p1 + w_pos_q[d * 3 + 2] * p2;
        const float* xp = x_q + (size_t)b * CC * NN + n;
#pragma unroll 4
        for (int c = 0; c < CC; c++) {
            float xv = xp[(size_t)c * NN];
            const float4* w4 = (const float4*)s_wqk[c];
#pragma unroll
            for (int i = 0; i < 4; i++) {
                float4 w = w4[i];
                acc[4 * i + 0] += w.x * xv; acc[4 * i + 1] += w.y * xv;
                acc[4 * i + 2] += w.z * xv; acc[4 * i + 3] += w.w * xv;
            }
        }
        float4* qp = (float4*)(g_Q + ((size_t)(b * NN + n)) * DD);
#pragma unroll
        for (int i = 0; i < 4; i++)
            qp[i] = make_float4(acc[4 * i], acc[4 * i + 1], acc[4 * i + 2], acc[4 * i + 3]);
    } else {
        float p0 = xyz_kv[(b * 3 + 0) * NN + n];
        float p1 = xyz_kv[(b * 3 + 1) * NN + n];
        float p2 = xyz_kv[(b * 3 + 2) * NN + n];
        float ak[DD], av[DD];
#pragma unroll
        for (int d = 0; d < DD; d++) {
            float pos = w_pos_kv[d * 3] * p0 + w_pos_kv[d * 3 + 1] * p1 + w_pos_kv[d * 3 + 2] * p2;
            ak[d] = pos;
            av[d] = pos + b_v[d];
        }
        const float* xp = x_kv + (size_t)b * CC * NN + n;
#pragma unroll 2
        for (int c = 0; c < CC; c++) {
            float xv = xp[(size_t)c * NN];
            const float4* wq4 = (const float4*)s_wqk[c];
            const float4* wv4 = (const float4*)s_wv[c];
#pragma unroll
            for (int i = 0; i < 4; i++) {
                float4 wq = wq4[i], wv = wv4[i];
                ak[4 * i + 0] += wq.x * xv; ak[4 * i + 1] += wq.y * xv;
                ak[4 * i + 2] += wq.z * xv; ak[4 * i + 3] += wq.w * xv;
                av[4 * i + 0] += wv.x * xv; av[4 * i + 1] += wv.y * xv;
                av[4 * i + 2] += wv.z * xv; av[4 * i + 3] += wv.w * xv;
            }
        }
        float4* kp = (float4*)(g_K + ((size_t)(b * NN + n)) * DD);
        float4* vp = (float4*)(g_V + ((size_t)(b * NN + n)) * DD);
#pragma unroll
        for (int i = 0; i < 4; i++) {
            kp[i] = make_float4(ak[4 * i] * LOG2E, ak[4 * i + 1] * LOG2E,
                                ak[4 * i + 2] * LOG2E, ak[4 * i + 3] * LOG2E);
            vp[i] = make_float4(av[4 * i], av[4 * i + 1], av[4 * i + 2], av[4 * i + 3]);
        }
    }
}

// ---------------------------------------------------------------------------
// Kernel 2: rowsum. 8 warps; lane = 4 rows; warp = 512-wide m-range;
// 32-row tiles double-buffered via cp.async.
// ---------------------------------------------------------------------------
__global__ __launch_bounds__(256, 1) void rowsum_kernel() {
    __shared__ __align__(16) float sk[8][2][32 * DD];
    __shared__ float sred[8][128];
    const int tid = threadIdx.x, lane = tid & 31, w = tid >> 5;
    const int b = blockIdx.y;
    const int row0 = blockIdx.x * 128 + lane * 4;

    ull qr[32];
    load_rows4(qr, g_Q + ((size_t)(b * NN + row0)) * DD);

    const char* kbase = (const char*)(g_K + ((size_t)b * NN + (size_t)w * 512) * DD);
    unsigned sb[2] = {(unsigned)__cvta_generic_to_shared(&sk[w][0][0]),
                      (unsigned)__cvta_generic_to_shared(&sk[w][1][0])};

    // prefetch tile 0
#pragma unroll
    for (int j = 0; j < 4; j++)
        cpa16(sb[0] + (lane + j * 32) * 16, kbase + (lane + j * 32) * 16);
    cp_commit();

    float sum[4] = {0.f, 0.f, 0.f, 0.f};
    for (int it = 0; it < 16; ++it) {
        __syncwarp();
        if (it + 1 < 16) {
            const char* src = kbase + (size_t)(it + 1) * 2048;
            unsigned d = sb[(it + 1) & 1];
#pragma unroll
            for (int j = 0; j < 4; j++)
                cpa16(d + (lane + j * 32) * 16, src + (lane + j * 32) * 16);
            cp_commit();
            cp_wait<1>();
        } else {
            cp_wait<0>();
        }
        __syncwarp();
        const float* ks = &sk[w][it & 1][0];
#pragma unroll 4
        for (int mm = 0; mm < 32; ++mm) {
            ull kk[8];
            ldk(kk, ks + mm * DD);
#pragma unroll
            for (int r = 0; r < 4; r++) sum[r] += ex2(dotrr(qr + r * 8, kk));
        }
    }
#pragma unroll
    for (int r = 0; r < 4; r++) sred[w][lane * 4 + r] = sum[r];
    __syncthreads();
    if (tid < 128) {
        float tot = 0.f;
#pragma unroll
        for (int j = 0; j < 8; j++) tot += sred[j][tid];
        g_rowinv[b * NN + blockIdx.x * 128 + tid] = 1.0f / tot;
    }
}

// ---------------------------------------------------------------------------
// Kernel 3: colsum. Same shape; q + rowinv staged, k in registers.
// ---------------------------------------------------------------------------
__global__ __launch_bounds__(256, 1) void colsum_kernel() {
    __shared__ __align__(16) float sq[8][2][32 * DD];
    __shared__ float sri[8][2][32];
    __shared__ float sred[8][128];
    const int tid = threadIdx.x, lane = tid & 31, w = tid >> 5;
    const int b = blockIdx.y;
    const int col0 = blockIdx.x * 128 + lane * 4;

    ull kr[32];
    load_rows4(kr, g_K + ((size_t)(b * NN + col0)) * DD);

    const char* qbase = (const char*)(g_Q + ((size_t)b * NN + (size_t)w * 512) * DD);
    const char* ribase = (const char*)(g_rowinv + b * NN + w * 512);
    unsigned sb[2] = {(unsigned)__cvta_generic_to_shared(&sq[w][0][0]),
                      (unsigned)__cvta_generic_to_shared(&sq[w][1][0])};
    unsigned rb[2] = {(unsigned)__cvta_generic_to_shared(&sri[w][0][0]),
                      (unsigned)__cvta_generic_to_shared(&sri[w][1][0])};

#pragma unroll
    for (int j = 0; j < 4; j++)
        cpa16(sb[0] + (lane + j * 32) * 16, qbase + (lane + j * 32) * 16);
    cpa4(rb[0] + lane * 4, ribase + lane * 4);
    cp_commit();

    float sum[4] = {0.f, 0.f, 0.f, 0.f};
    for (int it = 0; it < 16; ++it) {
        __syncwarp();
        if (it + 1 < 16) {
            int buf = (it + 1) & 1;
            const char* src = qbase + (size_t)(it + 1) * 2048;
#pragma unroll
            for (int j = 0; j < 4; j++)
                cpa16(sb[buf] + (lane + j * 32) * 16, src + (lane + j * 32) * 16);
            cpa4(rb[buf] + lane * 4, ribase + (size_t)(it + 1) * 128 + lane * 4);
            cp_commit();
            cp_wait<1>();
        } else {
            cp_wait<0>();
        }
        __syncwarp();
        const float* qs = &sq[w][it & 1][0];
        const float* ri = &sri[w][it & 1][0];
#pragma unroll 4
        for (int nn2 = 0; nn2 < 32; ++nn2) {
            ull kk[8];
            ldk(kk, qs + nn2 * DD);
            float r0 = ri[nn2];
#pragma unroll
            for (int r = 0; r < 4; r++) sum[r] += ex2(dotrr(kr + r * 8, kk)) * r0;
        }
    }
#pragma unroll
    for (int r = 0; r < 4; r++) sred[w][lane * 4 + r] = sum[r];
    __syncthreads();
    if (tid < 128) {
        float tot = 0.f;
#pragma unroll
        for (int j = 0; j < 8; j++) tot += sred[j][tid];
        g_colinv[b * NN + blockIdx.x * 128 + tid] = 1.0f / (1e-9f + tot);
    }
}

// ---------------------------------------------------------------------------
// Kernel 4: AV sweep + w_t transform + GN partial stats.
// 128 rows/block, 4 rows/lane, 8 warps; 16-m k/v tiles double-buffered.
// ---------------------------------------------------------------------------
__global__ __launch_bounds__(256, 1) void pass3_kernel(const float* __restrict__ w_t,
                                                       const float* __restrict__ b_t) {
    __shared__ __align__(16) float sbig[8192];   // 8 warps x 2 bufs x (256 k + 256 v)
    __shared__ float sci[8][2][16];
    __shared__ float swt[256];
    __shared__ float sred[1024];
    const int tid = threadIdx.x, lane = tid & 31, w = tid >> 5;
    const int b = blockIdx.y;
    const int row0 = blockIdx.x * 128 + lane * 4;

    swt[tid] = w_t[tid];

    ull qr[32];
    load_rows4(qr, g_Q + ((size_t)(b * NN + row0)) * DD);

    const char* kbase = (const char*)(g_K + ((size_t)b * NN + (size_t)w * 512) * DD);
    const char* vbase = (const char*)(g_V + ((size_t)b * NN + (size_t)w * 512) * DD);
    const char* cibase = (const char*)(g_colinv + b * NN + w * 512);
    float* warpbuf = sbig + w * 1024;
    unsigned kb[2] = {(unsigned)__cvta_generic_to_shared(warpbuf),
                      (unsigned)__cvta_generic_to_shared(warpbuf + 512)};
    unsigned cb[2] = {(unsigned)__cvta_generic_to_shared(&sci[w][0][0]),
                      (unsigned)__cvta_generic_to_shared(&sci[w][1][0])};

    // tile = 16 m-rows: k 1024B (64 x 16B chunks), v 1024B. 2 chunks each per lane.
    auto issue = [&](int it, int buf) {
        const char* ksrc = kbase + (size_t)it * 1024;
        const char* vsrc = vbase + (size_t)it * 1024;
#pragma unroll
        for (int j = 0; j < 2; j++) {
            cpa16(kb[buf] + (lane + j * 32) * 16, ksrc + (lane + j * 32) * 16);
            cpa16(kb[buf] + 1024 + (lane + j * 32) * 16, vsrc + (lane + j * 32) * 16);
        }
        if (lane < 16) cpa4(cb[buf] + lane * 4, cibase + (size_t)it * 64 + lane * 4);
        cp_commit();
    };
    issue(0, 0);

    ull xr[32];
#pragma unroll
    for (int i = 0; i < 32; i++) xr[i] = 0ULL;

    for (int it = 0; it < 32; ++it) {
        __syncwarp();
        if (it + 1 < 32) { issue(it + 1, (it + 1) & 1); cp_wait<1>(); }
        else             { cp_wait<0>(); }
        __syncwarp();
        const int buf = it & 1;
        const float* ks = warpbuf + buf * 512;
        const float* vs = ks + 256;
        const float* ci = &sci[w][buf][0];
#pragma unroll 2
        for (int mm = 0; mm < 16; ++mm) {
            ull kk[8];
            ldk(kk, ks + mm * DD);
            float c0 = ci[mm];
            float wgt[4];
#pragma unroll
            for (int r = 0; r < 4; r++) wgt[r] = ex2(dotrr(qr + r * 8, kk)) * c0;
            ull vv[8];
            ldk(vv, vs + mm * DD);
#pragma unroll
            for (int r = 0; r < 4; r++) {
                ull w2 = pack2(wgt[r], wgt[r]);
#pragma unroll
                for (int i = 0; i < 8; i++) xr[r * 8 + i] = fma2(w2, vv[i], xr[r * 8 + i]);
            }
        }
    }

    // reduce xr across 8 warps: 4 slots x 128 rows x 16 floats in sbig
    __syncthreads();
    if (w >= 4) {
        ull* d = (ull*)(sbig + ((size_t)(w - 4) * 128 + lane * 4) * DD);
#pragma unroll
        for (int i = 0; i < 32; i++) d[i] = xr[i];
    }
    __syncthreads();
    if (w < 4) {
        ull* d = (ull*)(sbig + ((size_t)w * 128 + lane * 4) * DD);
#pragma unroll
        for (int i = 0; i < 32; i++) d[i] = add2(d[i], xr[i]);
    }
    __syncthreads();

    if (tid < 128) {
        const int row = blockIdx.x * 128 + tid;
        float rinv = g_rowinv[b * NN + row];
        float xrf[DD];
        const float* s0 = sbig + tid * DD;
#pragma unroll
        for (int d = 0; d < DD; d++)
            xrf[d] = (s0[d] + s0[2048 + d] + s0[4096 + d] + s0[6144 + d]) * rinv;
        const float* qg = g_Q + ((size_t)(b * NN + row)) * DD;
        float diff[DD];
#pragma unroll
        for (int d = 0; d < DD; d++) diff[d] = qg[d] - xrf[d];
        float gs[4] = {0.f, 0.f, 0.f, 0.f}, gs2[4] = {0.f, 0.f, 0.f, 0.f};
#pragma unroll
        for (int o = 0; o < DD; o++) {
            float s = b_t[o];
#pragma unroll
            for (int d = 0; d < DD; d++) s += swt[o * DD + d] * diff[d];
            g_T[((size_t)(b * DD + o)) * NN + row] = s;
            gs[o >> 2] += s;
            gs2[o >> 2] += s * s;
        }
#pragma unroll
        for (int g = 0; g < 4; g++) {
            sred[tid * 8 + g] = gs[g];
            sred[tid * 8 + 4 + g] = gs2[g];
        }
    }
    __syncthreads();
    for (int s = 64; s > 0; s >>= 1) {
        if (tid < s) {
#pragma unroll
            for (int j = 0; j < 8; j++) sred[tid * 8 + j] += sred[(tid + s) * 8 + j];
        }
        __syncthreads();
    }
    if (tid < 8) g_part[((size_t)(b * NT + blockIdx.x)) * 8 + tid] = sred[tid];
}

// ---------------------------------------------------------------------------
// Kernel 5: finalize GN stats, relu, + q^T.
// ---------------------------------------------------------------------------
__global__ void final_kernel(const float* __restrict__ gamma, const float* __restrict__ beta,
                             float* __restrict__ out) {
    __shared__ float sq[128 * 17];
    __shared__ float ssc[DD], ssh[DD];
    const int b = blockIdx.y;
    const int tid = threadIdx.x;
    const int n0 = blockIdx.x * 128;
    if (tid < DD) {
        int g = tid >> 2;
        float s = 0.f, s2 = 0.f;
        for (int t = 0; t < NT; t++) {
            s += g_part[(b * NT + t) * 8 + g];
            s2 += g_part[(b * NT + t) * 8 + 4 + g];
        }
        float cnt = (float)(4 * NN);
        float mean = s / cnt;
        float var = s2 / cnt - mean * mean;
        float inv = rsqrtf(var + 1e-5f);
        float sc = gamma[tid] * inv;
        ssc[tid] = sc;
        ssh[tid] = beta[tid] - mean * sc;
    }
    const float* qsrc = g_Q + ((size_t)(b * NN + n0)) * DD;
    for (int i = tid; i < 128 * DD; i += 256) sq[(i >> 4) * 17 + (i & 15)] = qsrc[i];
    __syncthreads();
    for (int i = tid; i < 128 * DD; i += 256) {
        int c = i >> 7, j = i & 127;
        size_t idx = ((size_t)(b * DD + c)) * NN + n0 + j;
        float tv = g_T[idx];
        float r = fmaxf(tv * ssc[c] + ssh[c], 0.f);
        out[idx] = r + sq[j * 17 + c];
    }
}

extern "C" void kernel_launch(void* const* d_in, const int* in_sizes, int n_in,
                              void* d_out, int out_size) {
    const float* x_q      = (const float*)d_in[0];
    const float* x_kv     = (const float*)d_in[1];
    const float* xyz_q    = (const float*)d_in[2];
    const float* xyz_kv   = (const float*)d_in[3];
    const float* w_qk     = (const float*)d_in[4];
    const float* w_v      = (const float*)d_in[5];
    const float* b_v      = (const float*)d_in[6];
    const float* w_t      = (const float*)d_in[7];
    const float* b_t      = (const float*)d_in[8];
    const float* gamma    = (const float*)d_in[9];
    const float* beta     = (const float*)d_in[10];
    const float* w_pos_q  = (const float*)d_in[11];
    const float* w_pos_kv = (const float*)d_in[12];
    float* out = (float*)d_out;

    proj_kernel<<<dim3(32, 2, BB), 128>>>(x_q, x_kv, xyz_q, xyz_kv, w_qk, w_v, b_v,
                                          w_pos_q, w_pos_kv);
    rowsum_kernel<<<dim3(32, BB), 256>>>();
    colsum_kernel<<<dim3(32, BB), 256>>>();
    pass3_kernel<<<dim3(NT, BB), 256>>>(w_t, b_t);
    final_kernel<<<dim3(32, BB), 256>>>(gamma, beta, out);
}

// round 5
// speedup vs baseline: 1.1288x; 1.1197x over previous
#include <cuda_runtime.h>
#include <cuda_fp16.h>

#define BB 4
#define NN 4096
#define DD 16
#define CC 128
#define LOG2E 1.4426950408889634f
#define NT 32

typedef unsigned long long ull;

__device__ __align__(16) float g_Q[BB * NN * DD];
__device__ __align__(16) float g_K[BB * NN * DD];   // pre-scaled by log2(e)
__device__ __align__(16) float g_V[BB * NN * DD];
__device__ __align__(16) __half g_E[(size_t)BB * NN * NN];  // exp(e), [b][m][n]
__device__ float g_rowinv[BB * NN];
__device__ float g_colinv[BB * NN];
__device__ float g_T[BB * DD * NN];
__device__ float g_part[BB * NT * 8];

__device__ __forceinline__ ull pack2(float lo, float hi) {
    ull r; asm("mov.b64 %0, {%1, %2};" : "=l"(r) : "f"(lo), "f"(hi)); return r;
}
__device__ __forceinline__ void unpack2(ull v, float& lo, float& hi) {
    asm("mov.b64 {%0, %1}, %2;" : "=f"(lo), "=f"(hi) : "l"(v));
}
__device__ __forceinline__ ull fma2(ull a, ull b, ull c) {
    ull d; asm("fma.rn.f32x2 %0, %1, %2, %3;" : "=l"(d) : "l"(a), "l"(b), "l"(c)); return d;
}
__device__ __forceinline__ ull add2(ull a, ull b) {
    ull d; asm("add.rn.f32x2 %0, %1, %2;" : "=l"(d) : "l"(a), "l"(b)); return d;
}
__device__ __forceinline__ float ex2(float x) {
    float y; asm("ex2.approx.ftz.f32 %0, %1;" : "=f"(y) : "f"(x)); return y;
}
__device__ __forceinline__ void cpa16(unsigned dst, const void* src) {
    asm volatile("cp.async.ca.shared.global [%0], [%1], 16;" :: "r"(dst), "l"(src));
}
__device__ __forceinline__ void cp_commit() { asm volatile("cp.async.commit_group;"); }
template <int N> __device__ __forceinline__ void cp_wait() {
    asm volatile("cp.async.wait_group %0;" :: "n"(N));
}

__device__ __forceinline__ float dotrr(const ull* q, const ull* kk) {
    ull a0 = fma2(q[0], kk[0], 0ULL);
    ull a1 = fma2(q[1], kk[1], 0ULL);
    ull a2 = fma2(q[2], kk[2], 0ULL);
    ull a3 = fma2(q[3], kk[3], 0ULL);
    a0 = fma2(q[4], kk[4], a0);
    a1 = fma2(q[5], kk[5], a1);
    a2 = fma2(q[6], kk[6], a2);
    a3 = fma2(q[7], kk[7], a3);
    ull s = add2(add2(a0, a1), add2(a2, a3));
    float x, y; unpack2(s, x, y);
    return x + y;
}

__device__ __forceinline__ void load_rows4(ull* dst, const float* base) {
    const ulonglong2* p = (const ulonglong2*)base;
#pragma unroll
    for (int r = 0; r < 4; r++)
#pragma unroll
        for (int i = 0; i < 4; i++) {
            ulonglong2 t = p[r * 4 + i];
            dst[r * 8 + 2 * i] = t.x; dst[r * 8 + 2 * i + 1] = t.y;
        }
}
__device__ __forceinline__ void ldk(ull* kk, const float* p) {
    const ulonglong2* k2 = (const ulonglong2*)p;
#pragma unroll
    for (int i = 0; i < 4; i++) { ulonglong2 t = k2[i]; kk[2 * i] = t.x; kk[2 * i + 1] = t.y; }
}

// ---------------------------------------------------------------------------
// Kernel 1: projections. Q raw; K scaled by log2(e); V = wv@x + b_v + pos.
// ---------------------------------------------------------------------------
__global__ void proj_kernel(const float* __restrict__ x_q, const float* __restrict__ x_kv,
                            const float* __restrict__ xyz_q, const float* __restrict__ xyz_kv,
                            const float* __restrict__ w_qk, const float* __restrict__ w_v,
                            const float* __restrict__ b_v,
                            const float* __restrict__ w_pos_q, const float* __restrict__ w_pos_kv) {
    __shared__ __align__(16) float s_wqk[CC][DD];
    __shared__ __align__(16) float s_wv[CC][DD];
    const int b = blockIdx.z;
    const int isKV = blockIdx.y;
    const int n = blockIdx.x * 128 + threadIdx.x;
    for (int i = threadIdx.x; i < CC * DD; i += 128) {
        int d = i / CC, c = i % CC;
        s_wqk[c][d] = w_qk[i];
        s_wv[c][d] = w_v[i];
    }
    __syncthreads();
    if (isKV == 0) {
        float p0 = xyz_q[(b * 3 + 0) * NN + n];
        float p1 = xyz_q[(b * 3 + 1) * NN + n];
        float p2 = xyz_q[(b * 3 + 2) * NN + n];
        float acc[DD];
#pragma unroll
        for (int d = 0; d < DD; d++)
            acc[d] = w_pos_q[d * 3] * p0 + w_pos_q[d * 3 + 1] * p1 + w_pos_q[d * 3 + 2] * p2;
        const float* xp = x_q + (size_t)b * CC * NN + n;
#pragma unroll 4
        for (int c = 0; c < CC; c++) {
            float xv = xp[(size_t)c * NN];
            const float4* w4 = (const float4*)s_wqk[c];
#pragma unroll
            for (int i = 0; i < 4; i++) {
                float4 w = w4[i];
                acc[4 * i + 0] += w.x * xv; acc[4 * i + 1] += w.y * xv;
                acc[4 * i + 2] += w.z * xv; acc[4 * i + 3] += w.w * xv;
            }
        }
        float4* qp = (float4*)(g_Q + ((size_t)(b * NN + n)) * DD);
#pragma unroll
        for (int i = 0; i < 4; i++)
            qp[i] = make_float4(acc[4 * i], acc[4 * i + 1], acc[4 * i + 2], acc[4 * i + 3]);
    } else {
        float p0 = xyz_kv[(b * 3 + 0) * NN + n];
        float p1 = xyz_kv[(b * 3 + 1) * NN + n];
        float p2 = xyz_kv[(b * 3 + 2) * NN + n];
        float ak[DD], av[DD];
#pragma unroll
        for (int d = 0; d < DD; d++) {
            float pos = w_pos_kv[d * 3] * p0 + w_pos_kv[d * 3 + 1] * p1 + w_pos_kv[d * 3 + 2] * p2;
            ak[d] = pos;
            av[d] = pos + b_v[d];
        }
        const float* xp = x_kv + (size_t)b * CC * NN + n;
#pragma unroll 2
        for (int c = 0; c < CC; c++) {
            float xv = xp[(size_t)c * NN];
            const float4* wq4 = (const float4*)s_wqk[c];
            const float4* wv4 = (const float4*)s_wv[c];
#pragma unroll
            for (int i = 0; i < 4; i++) {
                float4 wq = wq4[i], wv = wv4[i];
                ak[4 * i + 0] += wq.x * xv; ak[4 * i + 1] += wq.y * xv;
                ak[4 * i + 2] += wq.z * xv; ak[4 * i + 3] += wq.w * xv;
                av[4 * i + 0] += wv.x * xv; av[4 * i + 1] += wv.y * xv;
                av[4 * i + 2] += wv.z * xv; av[4 * i + 3] += wv.w * xv;
            }
        }
        float4* kp = (float4*)(g_K + ((size_t)(b * NN + n)) * DD);
        float4* vp = (float4*)(g_V + ((size_t)(b * NN + n)) * DD);
#pragma unroll
        for (int i = 0; i < 4; i++) {
            kp[i] = make_float4(ak[4 * i] * LOG2E, ak[4 * i + 1] * LOG2E,
                                ak[4 * i + 2] * LOG2E, ak[4 * i + 3] * LOG2E);
            vp[i] = make_float4(av[4 * i], av[4 * i + 1], av[4 * i + 2], av[4 * i + 3]);
        }
    }
}

// ---------------------------------------------------------------------------
// Kernel 2: rowsum + store exp(e) fp16 to g_E[b][m][n].
// 8 warps; lane = 4 rows; warp = 512-wide m-range; double-buffered k tiles.
// Warp store per m: 32 lanes x 8B consecutive n = 256B coalesced.
// ---------------------------------------------------------------------------
__global__ __launch_bounds__(256, 1) void rowsum_kernel() {
    __shared__ __align__(16) float sk[8][2][32 * DD];
    __shared__ float sred[8][128];
    const int tid = threadIdx.x, lane = tid & 31, w = tid >> 5;
    const int b = blockIdx.y;
    const int n0blk = blockIdx.x * 128;
    const int row0 = n0blk + lane * 4;

    ull qr[32];
    load_rows4(qr, g_Q + ((size_t)(b * NN + row0)) * DD);

    const char* kbase = (const char*)(g_K + ((size_t)b * NN + (size_t)w * 512) * DD);
    __half* ebase = g_E + ((size_t)(b * NN + w * 512)) * NN + n0blk + lane * 4;
    unsigned sb[2] = {(unsigned)__cvta_generic_to_shared(&sk[w][0][0]),
                      (unsigned)__cvta_generic_to_shared(&sk[w][1][0])};

#pragma unroll
    for (int j = 0; j < 4; j++)
        cpa16(sb[0] + (lane + j * 32) * 16, kbase + (lane + j * 32) * 16);
    cp_commit();

    float sum[4] = {0.f, 0.f, 0.f, 0.f};
    for (int it = 0; it < 16; ++it) {
        __syncwarp();
        if (it + 1 < 16) {
            const char* src = kbase + (size_t)(it + 1) * 2048;
            unsigned d = sb[(it + 1) & 1];
#pragma unroll
            for (int j = 0; j < 4; j++)
                cpa16(d + (lane + j * 32) * 16, src + (lane + j * 32) * 16);
            cp_commit();
            cp_wait<1>();
        } else {
            cp_wait<0>();
        }
        __syncwarp();
        const float* ks = &sk[w][it & 1][0];
        __half* ep = ebase + (size_t)(it * 32) * NN;
#pragma unroll 4
        for (int mm = 0; mm < 32; ++mm) {
            ull kk[8];
            ldk(kk, ks + mm * DD);
            float e0 = ex2(dotrr(qr, kk));
            float e1 = ex2(dotrr(qr + 8, kk));
            float e2 = ex2(dotrr(qr + 16, kk));
            float e3 = ex2(dotrr(qr + 24, kk));
            sum[0] += e0; sum[1] += e1; sum[2] += e2; sum[3] += e3;
            union { __half2 h[2]; ull u; } cv;
            cv.h[0] = __floats2half2_rn(e0, e1);
            cv.h[1] = __floats2half2_rn(e2, e3);
            *(ull*)(ep + (size_t)mm * NN) = cv.u;
        }
    }
#pragma unroll
    for (int r = 0; r < 4; r++) sred[w][lane * 4 + r] = sum[r];
    __syncthreads();
    if (tid < 128) {
        float tot = 0.f;
#pragma unroll
        for (int j = 0; j < 8; j++) tot += sred[j][tid];
        g_rowinv[b * NN + n0blk + tid] = 1.0f / tot;
    }
}

// ---------------------------------------------------------------------------
// Kernel 3: colsum from stored E. Warp per m; lane sweeps n in 16B chunks.
// colinv[m] = 1/(1e-9 + sum_n E[m][n]*rowinv[n]). Memory-bound.
// ---------------------------------------------------------------------------
__global__ __launch_bounds__(256, 1) void colsum_kernel() {
    __shared__ __align__(16) float sri[NN];
    const int tid = threadIdx.x, lane = tid & 31, w = tid >> 5;
    const int b = blockIdx.y;
    const int m = blockIdx.x * 8 + w;
    {
        const float4* src = (const float4*)(g_rowinv + b * NN);
        float4* dst = (float4*)sri;
        for (int i = tid; i < NN / 4; i += 256) dst[i] = src[i];
    }
    __syncthreads();
    const __half* ep = g_E + ((size_t)(b * NN + m)) * NN;
    float s = 0.f;
#pragma unroll 4
    for (int c = 0; c < 16; c++) {
        int n = c * 256 + lane * 8;
        uint4 raw = *(const uint4*)(ep + n);
        const __half2* hp = (const __half2*)&raw;
        float2 f0 = __half22float2(hp[0]);
        float2 f1 = __half22float2(hp[1]);
        float2 f2 = __half22float2(hp[2]);
        float2 f3 = __half22float2(hp[3]);
        const float4* rp = (const float4*)(sri + n);
        float4 ra = rp[0], rb = rp[1];
        s += f0.x * ra.x + f0.y * ra.y + f1.x * ra.z + f1.y * ra.w;
        s += f2.x * rb.x + f2.y * rb.y + f3.x * rb.z + f3.y * rb.w;
    }
#pragma unroll
    for (int o = 16; o > 0; o >>= 1) s += __shfl_xor_sync(0xffffffffu, s, o);
    if (lane == 0) g_colinv[b * NN + m] = 1.0f / (1e-9f + s);
}

// ---------------------------------------------------------------------------
// Kernel 4: AV sweep reading stored E (no dots, no exp) + w_t + GN stats.
// 128 rows/block, 4 rows/lane, 8 warps; per 16-m subtile: stage V'=colinv*V,
// prefetch E into 16 LDG.64 registers.
// ---------------------------------------------------------------------------
__global__ __launch_bounds__(256, 1) void pass3_kernel(const float* __restrict__ w_t,
                                                       const float* __restrict__ b_t) {
    __shared__ __align__(16) float sbig[8192];   // warp v' tiles (w*1024), later xr slots
    __shared__ float swt[256];
    __shared__ float sred[1024];
    const int tid = threadIdx.x, lane = tid & 31, w = tid >> 5;
    const int b = blockIdx.y;
    const int n0blk = blockIdx.x * 128;
    const int row0 = n0blk + lane * 4;

    swt[tid] = w_t[tid];

    const float4* vsrc = (const float4*)(g_V + ((size_t)b * NN + (size_t)w * 512) * DD);
    const float* cisrc = g_colinv + b * NN + w * 512;
    const __half* ebase = g_E + ((size_t)(b * NN + w * 512)) * NN + n0blk + lane * 4;
    float* svw = sbig + w * 1024;   // 16 m x 16 floats used per tile

    ull xr[32];
#pragma unroll
    for (int i = 0; i < 32; i++) xr[i] = 0ULL;

    for (int it = 0; it < 32; ++it) {
        // prefetch E for this 16-m subtile: rows lane*4..+3 at 16 m values
        ull eh[16];
        {
            const __half* ep = ebase + (size_t)(it * 16) * NN;
#pragma unroll
            for (int j = 0; j < 16; j++) eh[j] = *(const ull*)(ep + (size_t)j * NN);
        }
        __syncwarp();
        // stage v' = colinv[m] * v[m][:]
        {
#pragma unroll
            for (int jj = 0; jj < 2; jj++) {
                int c = lane + jj * 32;            // chunk 0..63
                int ml = c >> 2;                   // m_local 0..15
                float ci = cisrc[it * 16 + ml];
                float4 v = vsrc[it * 64 + c];
                ((float4*)svw)[c] = make_float4(v.x * ci, v.y * ci, v.z * ci, v.w * ci);
            }
        }
        __syncwarp();
#pragma unroll 4
        for (int mm = 0; mm < 16; ++mm) {
            const __half2* hp = (const __half2*)&eh[mm];
            float2 wa = __half22float2(hp[0]);
            float2 wb = __half22float2(hp[1]);
            ull vv[8];
            ldk(vv, svw + mm * DD);
            ull w0 = pack2(wa.x, wa.x), w1 = pack2(wa.y, wa.y);
            ull w2 = pack2(wb.x, wb.x), w3 = pack2(wb.y, wb.y);
#pragma unroll
            for (int i = 0; i < 8; i++) {
                xr[i]      = fma2(w0, vv[i], xr[i]);
                xr[8 + i]  = fma2(w1, vv[i], xr[8 + i]);
                xr[16 + i] = fma2(w2, vv[i], xr[16 + i]);
                xr[24 + i] = fma2(w3, vv[i], xr[24 + i]);
            }
        }
        __syncwarp();
    }

    // reduce xr across 8 warps: 4 slots x 128 rows x 16 floats in sbig
    __syncthreads();
    if (w >= 4) {
        ull* d = (ull*)(sbig + ((size_t)(w - 4) * 128 + lane * 4) * DD);
#pragma unroll
        for (int i = 0; i < 32; i++) d[i] = xr[i];
    }
    __syncthreads();
    if (w < 4) {
        ull* d = (ull*)(sbig + ((size_t)w * 128 + lane * 4) * DD);
#pragma unroll
        for (int i = 0; i < 32; i++) d[i] = add2(d[i], xr[i]);
    }
    __syncthreads();

    if (tid < 128) {
        const int row = n0blk + tid;
        float rinv = g_rowinv[b * NN + row];
        float xrf[DD];
        const float* s0 = sbig + tid * DD;
#pragma unroll
        for (int d = 0; d < DD; d++)
            xrf[d] = (s0[d] + s0[2048 + d] + s0[4096 + d] + s0[6144 + d]) * rinv;
        const float* qg = g_Q + ((size_t)(b * NN + row)) * DD;
        float diff[DD];
#pragma unroll
        for (int d = 0; d < DD; d++) diff[d] = qg[d] - xrf[d];
        float gs[4] = {0.f, 0.f, 0.f, 0.f}, gs2[4] = {0.f, 0.f, 0.f, 0.f};
#pragma unroll
        for (int o = 0; o < DD; o++) {
            float s = b_t[o];
#pragma unroll
            for (int d = 0; d < DD; d++) s += swt[o * DD + d] * diff[d];
            g_T[((size_t)(b * DD + o)) * NN + row] = s;
            gs[o >> 2] += s;
            gs2[o >> 2] += s * s;
        }
#pragma unroll
        for (int g = 0; g < 4; g++) {
            sred[tid * 8 + g] = gs[g];
            sred[tid * 8 + 4 + g] = gs2[g];
        }
    }
    __syncthreads();
    for (int s = 64; s > 0; s >>= 1) {
        if (tid < s) {
#pragma unroll
            for (int j = 0; j < 8; j++) sred[tid * 8 + j] += sred[(tid + s) * 8 + j];
        }
        __syncthreads();
    }
    if (tid < 8) g_part[((size_t)(b * NT + blockIdx.x)) * 8 + tid] = sred[tid];
}

// ---------------------------------------------------------------------------
// Kernel 5: finalize GN stats, relu, + q^T.
// ---------------------------------------------------------------------------
__global__ void final_kernel(const float* __restrict__ gamma, const float* __restrict__ beta,
                             float* __restrict__ out) {
    __shared__ float sq[128 * 17];
    __shared__ float ssc[DD], ssh[DD];
    const int b = blockIdx.y;
    const int tid = threadIdx.x;
    const int n0 = blockIdx.x * 128;
    if (tid < DD) {
        int g = tid >> 2;
        float s = 0.f, s2 = 0.f;
        for (int t = 0; t < NT; t++) {
            s += g_part[(b * NT + t) * 8 + g];
            s2 += g_part[(b * NT + t) * 8 + 4 + g];
        }
        float cnt = (float)(4 * NN);
        float mean = s / cnt;
        float var = s2 / cnt - mean * mean;
        float inv = rsqrtf(var + 1e-5f);
        float sc = gamma[tid] * inv;
        ssc[tid] = sc;
        ssh[tid] = beta[tid] - mean * sc;
    }
    const float* qsrc = g_Q + ((size_t)(b * NN + n0)) * DD;
    for (int i = tid; i < 128 * DD; i += 256) sq[(i >> 4) * 17 + (i & 15)] = qsrc[i];
    __syncthreads();
    for (int i = tid; i < 128 * DD; i += 256) {
        int c = i >> 7, j = i & 127;
        size_t idx = ((size_t)(b * DD + c)) * NN + n0 + j;
        float tv = g_T[idx];
        float r = fmaxf(tv * ssc[c] + ssh[c], 0.f);
        out[idx] = r + sq[j * 17 + c];
    }
}

extern "C" void kernel_launch(void* const* d_in, const int* in_sizes, int n_in,
                              void* d_out, int out_size) {
    const float* x_q      = (const float*)d_in[0];
    const float* x_kv     = (const float*)d_in[1];
    const float* xyz_q    = (const float*)d_in[2];
    const float* xyz_kv   = (const float*)d_in[3];
    const float* w_qk     = (const float*)d_in[4];
    const float* w_v      = (const float*)d_in[5];
    const float* b_v      = (const float*)d_in[6];
    const float* w_t      = (const float*)d_in[7];
    const float* b_t      = (const float*)d_in[8];
    const float* gamma    = (const float*)d_in[9];
    const float* beta     = (const float*)d_in[10];
    const float* w_pos_q  = (const float*)d_in[11];
    const float* w_pos_kv = (const float*)d_in[12];
    float* out = (float*)d_out;

    proj_kernel<<<dim3(32, 2, BB), 128>>>(x_q, x_kv, xyz_q, xyz_kv, w_qk, w_v, b_v,
                                          w_pos_q, w_pos_kv);
    rowsum_kernel<<<dim3(32, BB), 256>>>();
    colsum_kernel<<<dim3(512, BB), 256>>>();
    pass3_kernel<<<dim3(NT, BB), 256>>>(w_t, b_t);
    final_kernel<<<dim3(32, BB), 256>>>(gamma, beta, out);
}

// round 6
// speedup vs baseline: 1.1922x; 1.0562x over previous
#include <cuda_runtime.h>
#include <cuda_fp16.h>

#define BB 4
#define NN 4096
#define DD 16
#define CC 128
#define LOG2E 1.4426950408889634f
#define NT 32

typedef unsigned long long ull;

__device__ __align__(16) float g_Q[BB * NN * DD];
__device__ __align__(16) float g_K[BB * NN * DD];   // pre-scaled by log2(e)
__device__ __align__(16) float g_V[BB * NN * DD];
__device__ __align__(16) __half g_E[(size_t)BB * NN * NN];  // exp(e), [b][m][n]
__device__ float g_rowinv[BB * NN];
__device__ float g_colinv[BB * NN];
__device__ float g_T[BB * DD * NN];
__device__ float g_part[BB * NT * 8];

__device__ __forceinline__ ull pack2(float lo, float hi) {
    ull r; asm("mov.b64 %0, {%1, %2};" : "=l"(r) : "f"(lo), "f"(hi)); return r;
}
__device__ __forceinline__ void unpack2(ull v, float& lo, float& hi) {
    asm("mov.b64 {%0, %1}, %2;" : "=f"(lo), "=f"(hi) : "l"(v));
}
__device__ __forceinline__ ull fma2(ull a, ull b, ull c) {
    ull d; asm("fma.rn.f32x2 %0, %1, %2, %3;" : "=l"(d) : "l"(a), "l"(b), "l"(c)); return d;
}
__device__ __forceinline__ ull add2(ull a, ull b) {
    ull d; asm("add.rn.f32x2 %0, %1, %2;" : "=l"(d) : "l"(a), "l"(b)); return d;
}
__device__ __forceinline__ float ex2(float x) {
    float y; asm("ex2.approx.ftz.f32 %0, %1;" : "=f"(y) : "f"(x)); return y;
}
__device__ __forceinline__ void cpa16(unsigned dst, const void* src) {
    asm volatile("cp.async.ca.shared.global [%0], [%1], 16;" :: "r"(dst), "l"(src));
}
__device__ __forceinline__ void cp_commit() { asm volatile("cp.async.commit_group;"); }
template <int N> __device__ __forceinline__ void cp_wait() {
    asm volatile("cp.async.wait_group %0;" :: "n"(N));
}

__device__ __forceinline__ float dotrr(const ull* q, const ull* kk) {
    ull a0 = fma2(q[0], kk[0], 0ULL);
    ull a1 = fma2(q[1], kk[1], 0ULL);
    ull a2 = fma2(q[2], kk[2], 0ULL);
    ull a3 = fma2(q[3], kk[3], 0ULL);
    a0 = fma2(q[4], kk[4], a0);
    a1 = fma2(q[5], kk[5], a1);
    a2 = fma2(q[6], kk[6], a2);
    a3 = fma2(q[7], kk[7], a3);
    ull s = add2(add2(a0, a1), add2(a2, a3));
    float x, y; unpack2(s, x, y);
    return x + y;
}

__device__ __forceinline__ void load_rows4(ull* dst, const float* base) {
    const ulonglong2* p = (const ulonglong2*)base;
#pragma unroll
    for (int r = 0; r < 4; r++)
#pragma unroll
        for (int i = 0; i < 4; i++) {
            ulonglong2 t = p[r * 4 + i];
            dst[r * 8 + 2 * i] = t.x; dst[r * 8 + 2 * i + 1] = t.y;
        }
}
__device__ __forceinline__ void ldk(ull* kk, const float* p) {
    const ulonglong2* k2 = (const ulonglong2*)p;
#pragma unroll
    for (int i = 0; i < 4; i++) { ulonglong2 t = k2[i]; kk[2 * i] = t.x; kk[2 * i + 1] = t.y; }
}

// ---------------------------------------------------------------------------
// Kernel 1: projections. Q raw; K scaled by log2(e); V = wv@x + b_v + pos.
// ---------------------------------------------------------------------------
__global__ void proj_kernel(const float* __restrict__ x_q, const float* __restrict__ x_kv,
                            const float* __restrict__ xyz_q, const float* __restrict__ xyz_kv,
                            const float* __restrict__ w_qk, const float* __restrict__ w_v,
                            const float* __restrict__ b_v,
                            const float* __restrict__ w_pos_q, const float* __restrict__ w_pos_kv) {
    __shared__ __align__(16) float s_wqk[CC][DD];
    __shared__ __align__(16) float s_wv[CC][DD];
    const int b = blockIdx.z;
    const int isKV = blockIdx.y;
    const int n = blockIdx.x * 128 + threadIdx.x;
    for (int i = threadIdx.x; i < CC * DD; i += 128) {
        int d = i / CC, c = i % CC;
        s_wqk[c][d] = w_qk[i];
        s_wv[c][d] = w_v[i];
    }
    __syncthreads();
    if (isKV == 0) {
        float p0 = xyz_q[(b * 3 + 0) * NN + n];
        float p1 = xyz_q[(b * 3 + 1) * NN + n];
        float p2 = xyz_q[(b * 3 + 2) * NN + n];
        float acc[DD];
#pragma unroll
        for (int d = 0; d < DD; d++)
            acc[d] = w_pos_q[d * 3] * p0 + w_pos_q[d * 3 + 1] * p1 + w_pos_q[d * 3 + 2] * p2;
        const float* xp = x_q + (size_t)b * CC * NN + n;
#pragma unroll 4
        for (int c = 0; c < CC; c++) {
            float xv = xp[(size_t)c * NN];
            const float4* w4 = (const float4*)s_wqk[c];
#pragma unroll
            for (int i = 0; i < 4; i++) {
                float4 w = w4[i];
                acc[4 * i + 0] += w.x * xv; acc[4 * i + 1] += w.y * xv;
                acc[4 * i + 2] += w.z * xv; acc[4 * i + 3] += w.w * xv;
            }
        }
        float4* qp = (float4*)(g_Q + ((size_t)(b * NN + n)) * DD);
#pragma unroll
        for (int i = 0; i < 4; i++)
            qp[i] = make_float4(acc[4 * i], acc[4 * i + 1], acc[4 * i + 2], acc[4 * i + 3]);
    } else {
        float p0 = xyz_kv[(b * 3 + 0) * NN + n];
        float p1 = xyz_kv[(b * 3 + 1) * NN + n];
        float p2 = xyz_kv[(b * 3 + 2) * NN + n];
        float ak[DD], av[DD];
#pragma unroll
        for (int d = 0; d < DD; d++) {
            float pos = w_pos_kv[d * 3] * p0 + w_pos_kv[d * 3 + 1] * p1 + w_pos_kv[d * 3 + 2] * p2;
            ak[d] = pos;
            av[d] = pos + b_v[d];
        }
        const float* xp = x_kv + (size_t)b * CC * NN + n;
#pragma unroll 2
        for (int c = 0; c < CC; c++) {
            float xv = xp[(size_t)c * NN];
            const float4* wq4 = (const float4*)s_wqk[c];
            const float4* wv4 = (const float4*)s_wv[c];
#pragma unroll
            for (int i = 0; i < 4; i++) {
                float4 wq = wq4[i], wv = wv4[i];
                ak[4 * i + 0] += wq.x * xv; ak[4 * i + 1] += wq.y * xv;
                ak[4 * i + 2] += wq.z * xv; ak[4 * i + 3] += wq.w * xv;
                av[4 * i + 0] += wv.x * xv; av[4 * i + 1] += wv.y * xv;
                av[4 * i + 2] += wv.z * xv; av[4 * i + 3] += wv.w * xv;
            }
        }
        float4* kp = (float4*)(g_K + ((size_t)(b * NN + n)) * DD);
        float4* vp = (float4*)(g_V + ((size_t)(b * NN + n)) * DD);
#pragma unroll
        for (int i = 0; i < 4; i++) {
            kp[i] = make_float4(ak[4 * i] * LOG2E, ak[4 * i + 1] * LOG2E,
                                ak[4 * i + 2] * LOG2E, ak[4 * i + 3] * LOG2E);
            vp[i] = make_float4(av[4 * i], av[4 * i + 1], av[4 * i + 2], av[4 * i + 3]);
        }
    }
}

// ---------------------------------------------------------------------------
// Kernel 2: rowsum + store exp(e) fp16 to g_E[b][m][n].
// ---------------------------------------------------------------------------
__global__ __launch_bounds__(256, 1) void rowsum_kernel() {
    __shared__ __align__(16) float sk[8][2][32 * DD];
    __shared__ float sred[8][128];
    const int tid = threadIdx.x, lane = tid & 31, w = tid >> 5;
    const int b = blockIdx.y;
    const int n0blk = blockIdx.x * 128;
    const int row0 = n0blk + lane * 4;

    ull qr[32];
    load_rows4(qr, g_Q + ((size_t)(b * NN + row0)) * DD);

    const char* kbase = (const char*)(g_K + ((size_t)b * NN + (size_t)w * 512) * DD);
    __half* ebase = g_E + ((size_t)(b * NN + w * 512)) * NN + n0blk + lane * 4;
    unsigned sb[2] = {(unsigned)__cvta_generic_to_shared(&sk[w][0][0]),
                      (unsigned)__cvta_generic_to_shared(&sk[w][1][0])};

#pragma unroll
    for (int j = 0; j < 4; j++)
        cpa16(sb[0] + (lane + j * 32) * 16, kbase + (lane + j * 32) * 16);
    cp_commit();

    float sum[4] = {0.f, 0.f, 0.f, 0.f};
    for (int it = 0; it < 16; ++it) {
        __syncwarp();
        if (it + 1 < 16) {
            const char* src = kbase + (size_t)(it + 1) * 2048;
            unsigned d = sb[(it + 1) & 1];
#pragma unroll
            for (int j = 0; j < 4; j++)
                cpa16(d + (lane + j * 32) * 16, src + (lane + j * 32) * 16);
            cp_commit();
            cp_wait<1>();
        } else {
            cp_wait<0>();
        }
        __syncwarp();
        const float* ks = &sk[w][it & 1][0];
        __half* ep = ebase + (size_t)(it * 32) * NN;
#pragma unroll 4
        for (int mm = 0; mm < 32; ++mm) {
            ull kk[8];
            ldk(kk, ks + mm * DD);
            float e0 = ex2(dotrr(qr, kk));
            float e1 = ex2(dotrr(qr + 8, kk));
            float e2 = ex2(dotrr(qr + 16, kk));
            float e3 = ex2(dotrr(qr + 24, kk));
            sum[0] += e0; sum[1] += e1; sum[2] += e2; sum[3] += e3;
            union { __half2 h[2]; ull u; } cv;
            cv.h[0] = __floats2half2_rn(e0, e1);
            cv.h[1] = __floats2half2_rn(e2, e3);
            *(ull*)(ep + (size_t)mm * NN) = cv.u;
        }
    }
#pragma unroll
    for (int r = 0; r < 4; r++) sred[w][lane * 4 + r] = sum[r];
    __syncthreads();
    if (tid < 128) {
        float tot = 0.f;
#pragma unroll
        for (int j = 0; j < 8; j++) tot += sred[j][tid];
        g_rowinv[b * NN + n0blk + tid] = 1.0f / tot;
    }
}

// ---------------------------------------------------------------------------
// Kernel 3: colsum from stored E. Warp per m; two accumulators, deep unroll.
// ---------------------------------------------------------------------------
__global__ __launch_bounds__(256, 1) void colsum_kernel() {
    __shared__ __align__(16) float sri[NN];
    const int tid = threadIdx.x, lane = tid & 31, w = tid >> 5;
    const int b = blockIdx.y;
    const int m = blockIdx.x * 8 + w;
    {
        const float4* src = (const float4*)(g_rowinv + b * NN);
        float4* dst = (float4*)sri;
        for (int i = tid; i < NN / 4; i += 256) dst[i] = src[i];
    }
    __syncthreads();
    const __half* ep = g_E + ((size_t)(b * NN + m)) * NN;
    float s0 = 0.f, s1 = 0.f;
#pragma unroll
    for (int c = 0; c < 8; c++) {
        int n = c * 512 + lane * 16;
        uint4 ra = *(const uint4*)(ep + n);
        uint4 rb = *(const uint4*)(ep + n + 8);
        const __half2* ha = (const __half2*)&ra;
        const __half2* hb = (const __half2*)&rb;
        const float4* rp = (const float4*)(sri + n);
        float4 p0 = rp[0], p1 = rp[1], p2 = rp[2], p3 = rp[3];
        float2 f;
        f = __half22float2(ha[0]); s0 += f.x * p0.x + f.y * p0.y;
        f = __half22float2(ha[1]); s1 += f.x * p0.z + f.y * p0.w;
        f = __half22float2(ha[2]); s0 += f.x * p1.x + f.y * p1.y;
        f = __half22float2(ha[3]); s1 += f.x * p1.z + f.y * p1.w;
        f = __half22float2(hb[0]); s0 += f.x * p2.x + f.y * p2.y;
        f = __half22float2(hb[1]); s1 += f.x * p2.z + f.y * p2.w;
        f = __half22float2(hb[2]); s0 += f.x * p3.x + f.y * p3.y;
        f = __half22float2(hb[3]); s1 += f.x * p3.z + f.y * p3.w;
    }
    float s = s0 + s1;
#pragma unroll
    for (int o = 16; o > 0; o >>= 1) s += __shfl_xor_sync(0xffffffffu, s, o);
    if (lane == 0) g_colinv[b * NN + m] = 1.0f / (1e-9f + s);
}

// ---------------------------------------------------------------------------
// Kernel 4: AV sweep, fully pipelined: E in register double-buffer (prefetch
// distance 1 tile), V+colinv via cp.async double-buffer. ci folded into weights.
// ---------------------------------------------------------------------------
__global__ __launch_bounds__(256, 1) void pass3_kernel(const float* __restrict__ w_t,
                                                       const float* __restrict__ b_t) {
    __shared__ __align__(16) float sbig[8192];   // mainloop: V tiles [0,4096); reduce: all
    __shared__ __align__(16) float sci[8][2][16];
    __shared__ float swt[256];
    __shared__ float sred[1024];
    const int tid = threadIdx.x, lane = tid & 31, w = tid >> 5;
    const int b = blockIdx.y;
    const int n0blk = blockIdx.x * 128;

    swt[tid] = w_t[tid];

    const char* vbase = (const char*)(g_V + ((size_t)b * NN + (size_t)w * 512) * DD);
    const char* cibase = (const char*)(g_colinv + b * NN + w * 512);
    const __half* ebase = g_E + ((size_t)(b * NN + w * 512)) * NN + n0blk + lane * 4;
    float* svw = sbig + w * 512;   // two 256-float V buffers per warp
    unsigned vb[2] = {(unsigned)__cvta_generic_to_shared(svw),
                      (unsigned)__cvta_generic_to_shared(svw + 256)};
    unsigned cb[2] = {(unsigned)__cvta_generic_to_shared(&sci[w][0][0]),
                      (unsigned)__cvta_generic_to_shared(&sci[w][1][0])};

    ull xr[32];
#pragma unroll
    for (int i = 0; i < 32; i++) xr[i] = 0ULL;

    auto issue = [&](int it, int buf) {
        const char* vsrc = vbase + (size_t)it * 1024;
        cpa16(vb[buf] + lane * 16, vsrc + lane * 16);
        cpa16(vb[buf] + 512 + lane * 16, vsrc + 512 + lane * 16);
        if (lane < 4) cpa16(cb[buf] + lane * 16, cibase + (size_t)it * 64 + lane * 16);
        cp_commit();
    };
    auto ld_eh = [&](ull* eh, int it) {
        const __half* ep = ebase + (size_t)(it * 16) * NN;
#pragma unroll
        for (int j = 0; j < 16; j++) eh[j] = *(const ull*)(ep + (size_t)j * NN);
    };
    auto compute = [&](const ull* eh, int buf) {
        const float* vs = svw + buf * 256;
        const float* ci = &sci[w][buf][0];
#pragma unroll
        for (int mm = 0; mm < 16; ++mm) {
            const __half2* hp = (const __half2*)&eh[mm];
            float2 wa = __half22float2(hp[0]);
            float2 wb = __half22float2(hp[1]);
            float c0 = ci[mm];
            wa.x *= c0; wa.y *= c0; wb.x *= c0; wb.y *= c0;
            ull vv[8];
            ldk(vv, vs + mm * DD);
            ull w0 = pack2(wa.x, wa.x), w1 = pack2(wa.y, wa.y);
            ull w2 = pack2(wb.x, wb.x), w3 = pack2(wb.y, wb.y);
#pragma unroll
            for (int i = 0; i < 8; i++) {
                xr[i]      = fma2(w0, vv[i], xr[i]);
                xr[8 + i]  = fma2(w1, vv[i], xr[8 + i]);
                xr[16 + i] = fma2(w2, vv[i], xr[16 + i]);
                xr[24 + i] = fma2(w3, vv[i], xr[24 + i]);
            }
        }
    };

    ull ehA[16], ehB[16];
    issue(0, 0);
    issue(1, 1);
    ld_eh(ehA, 0);
    cp_wait<1>();
    __syncwarp();

#pragma unroll 1
    for (int it = 0; it < 32; it += 2) {
        ld_eh(ehB, it + 1);              // E prefetch in flight over compute A
        compute(ehA, 0);
        __syncwarp();
        if (it + 2 < 32) { issue(it + 2, 0); cp_wait<1>(); } else { cp_wait<0>(); }
        __syncwarp();
        if (it + 2 < 32) ld_eh(ehA, it + 2);   // E prefetch over compute B
        compute(ehB, 1);
        __syncwarp();
        if (it + 3 < 32) { issue(it + 3, 1); cp_wait<1>(); } else { cp_wait<0>(); }
        __syncwarp();
    }

    // reduce xr across 8 warps: 4 slots x 128 rows x 16 floats in sbig
    __syncthreads();
    if (w >= 4) {
        ull* d = (ull*)(sbig + ((size_t)(w - 4) * 128 + lane * 4) * DD);
#pragma unroll
        for (int i = 0; i < 32; i++) d[i] = xr[i];
    }
    __syncthreads();
    if (w < 4) {
        ull* d = (ull*)(sbig + ((size_t)w * 128 + lane * 4) * DD);
#pragma unroll
        for (int i = 0; i < 32; i++) d[i] = add2(d[i], xr[i]);
    }
    __syncthreads();

    if (tid < 128) {
        const int row = n0blk + tid;
        float rinv = g_rowinv[b * NN + row];
        float xrf[DD];
        const float* s0 = sbig + tid * DD;
#pragma unroll
        for (int d = 0; d < DD; d++)
            xrf[d] = (s0[d] + s0[2048 + d] + s0[4096 + d] + s0[6144 + d]) * rinv;
        const float* qg = g_Q + ((size_t)(b * NN + row)) * DD;
        float diff[DD];
#pragma unroll
        for (int d = 0; d < DD; d++) diff[d] = qg[d] - xrf[d];
        float gs[4] = {0.f, 0.f, 0.f, 0.f}, gs2[4] = {0.f, 0.f, 0.f, 0.f};
#pragma unroll
        for (int o = 0; o < DD; o++) {
            float s = b_t[o];
#pragma unroll
            for (int d = 0; d < DD; d++) s += swt[o * DD + d] * diff[d];
            g_T[((size_t)(b * DD + o)) * NN + row] = s;
            gs[o >> 2] += s;
            gs2[o >> 2] += s * s;
        }
#pragma unroll
        for (int g = 0; g < 4; g++) {
            sred[tid * 8 + g] = gs[g];
            sred[tid * 8 + 4 + g] = gs2[g];
        }
    }
    __syncthreads();
    for (int s = 64; s > 0; s >>= 1) {
        if (tid < s) {
#pragma unroll
            for (int j = 0; j < 8; j++) sred[tid * 8 + j] += sred[(tid + s) * 8 + j];
        }
        __syncthreads();
    }
    if (tid < 8) g_part[((size_t)(b * NT + blockIdx.x)) * 8 + tid] = sred[tid];
}

// ---------------------------------------------------------------------------
// Kernel 5: finalize GN stats, relu, + q^T.
// ---------------------------------------------------------------------------
__global__ void final_kernel(const float* __restrict__ gamma, const float* __restrict__ beta,
                             float* __restrict__ out) {
    __shared__ float sq[128 * 17];
    __shared__ float ssc[DD], ssh[DD];
    const int b = blockIdx.y;
    const int tid = threadIdx.x;
    const int n0 = blockIdx.x * 128;
    if (tid < DD) {
        int g = tid >> 2;
        float s = 0.f, s2 = 0.f;
        for (int t = 0; t < NT; t++) {
            s += g_part[(b * NT + t) * 8 + g];
            s2 += g_part[(b * NT + t) * 8 + 4 + g];
        }
        float cnt = (float)(4 * NN);
        float mean = s / cnt;
        float var = s2 / cnt - mean * mean;
        float inv = rsqrtf(var + 1e-5f);
        float sc = gamma[tid] * inv;
        ssc[tid] = sc;
        ssh[tid] = beta[tid] - mean * sc;
    }
    const float* qsrc = g_Q + ((size_t)(b * NN + n0)) * DD;
    for (int i = tid; i < 128 * DD; i += 256) sq[(i >> 4) * 17 + (i & 15)] = qsrc[i];
    __syncthreads();
    for (int i = tid; i < 128 * DD; i += 256) {
        int c = i >> 7, j = i & 127;
        size_t idx = ((size_t)(b * DD + c)) * NN + n0 + j;
        float tv = g_T[idx];
        float r = fmaxf(tv * ssc[c] + ssh[c], 0.f);
        out[idx] = r + sq[j * 17 + c];
    }
}

extern "C" void kernel_launch(void* const* d_in, const int* in_sizes, int n_in,
                              void* d_out, int out_size) {
    const float* x_q      = (const float*)d_in[0];
    const float* x_kv     = (const float*)d_in[1];
    const float* xyz_q    = (const float*)d_in[2];
    const float* xyz_kv   = (const float*)d_in[3];
    const float* w_qk     = (const float*)d_in[4];
    const float* w_v      = (const float*)d_in[5];
    const float* b_v      = (const float*)d_in[6];
    const float* w_t      = (const float*)d_in[7];
    const float* b_t      = (const float*)d_in[8];
    const float* gamma    = (const float*)d_in[9];
    const float* beta     = (const float*)d_in[10];
    const float* w_pos_q  = (const float*)d_in[11];
    const float* w_pos_kv = (const float*)d_in[12];
    float* out = (float*)d_out;

    proj_kernel<<<dim3(32, 2, BB), 128>>>(x_q, x_kv, xyz_q, xyz_kv, w_qk, w_v, b_v,
                                          w_pos_q, w_pos_kv);
    rowsum_kernel<<<dim3(32, BB), 256>>>();
    colsum_kernel<<<dim3(512, BB), 256>>>();
    pass3_kernel<<<dim3(NT, BB), 256>>>(w_t, b_t);
    final_kernel<<<dim3(32, BB), 256>>>(gamma, beta, out);
}